// round 12
// baseline (speedup 1.0000x reference)
#include <cuda_runtime.h>
#include <cuda_bf16.h>
#include <math.h>

// x: [B=2, T=64, C=16, H=128, W=128] f32; qkv conv 3x3 pad1 (16->16),
// nh=8, hc=2, D=32768; causal softmax T=64; out conv 3x3 (16->16).
#define HW 16384
typedef unsigned long long ull;

#define QK_SPLITS 32
#define QK_SUBS   16

// ---------------- packed fp32x2 helpers (FFMA2 path, 2x fp32 tput) --------
__device__ __forceinline__ ull pk2(float lo, float hi) {
    ull r;
    asm("mov.b64 %0, {%1, %2};"
        : "=l"(r) : "r"(__float_as_uint(lo)), "r"(__float_as_uint(hi)));
    return r;
}
__device__ __forceinline__ void fma2(ull& d, ull a, ull b) {
    asm("fma.rn.f32x2 %0, %1, %2, %0;" : "+l"(d) : "l"(a), "l"(b));
}
__device__ __forceinline__ float2 upk(ull v) {
    unsigned lo, hi;
    asm("mov.b64 {%0, %1}, %2;" : "=r"(lo), "=r"(hi) : "l"(v));
    return make_float2(__uint_as_float(lo), __uint_as_float(hi));
}

// ---------------- scratch ----------------
__device__ float         g_q[2*64*16*16384];   // y (attention output)
__device__ float         g_v[2*64*16*16384];   // v (fp32: precision-critical)
__device__ __nv_bfloat16 g_qh[2*64*16*16384];  // q in bf16 (only used in dot)
__device__ __nv_bfloat16 g_kh[2*64*16*16384];  // k in bf16
__device__ float g_part[QK_SPLITS*16*64*64];   // QK^T partials per k-split
__device__ float g_att[16*64*64];              // softmax probs, [bh][s][t]

// ---------------- 3x3 conv, channel-pair FFMA2, pipelined staging ---------
// f32x2 lanes = two OUTPUT CHANNELS. Tile 32w x 8h, block 256 thr =
// 4 channel groups x 64 px slots; thread = 4 pixels x PPG channel-pairs.
// Input halo tile staged in TWO channel groups (ic 0..7 / 8..15); group B's
// LDG latency hides under group A's compute.
template<int NCONV>
__global__ void __launch_bounds__(256) conv3x3_kernel(
    const float* __restrict__ xin,
    const float* __restrict__ w0, const float* __restrict__ b0,
    const float* __restrict__ w1, const float* __restrict__ b1,
    const float* __restrict__ w2, const float* __restrict__ b2,
    float* __restrict__ out_final)
{
    constexpr int NPAIR = NCONV * 8;     // channel pairs total
    constexpr int PPG   = NPAIR / 4;     // pairs per channel group
    extern __shared__ ull dyn[];
    ull*   s_w2 = dyn;                          // NPAIR*16ic*10 packed (wA,wB)
    float* s_in = (float*)(dyn + NPAIR*160);    // 16c x 10row x 35 halo tile
    float* s_b  = s_in + 16*350;                // NCONV*16 biases

    const int tid = threadIdx.x;
    const int bt  = blockIdx.y;                 // image 0..127
    const int th0 = (blockIdx.x >> 2) * 8;      // tile origin h
    const int tw0 = (blockIdx.x & 3) * 32;      // tile origin w

    const float* x = (NCONV == 3) ? xin : g_q;  // final conv reads y (on g_q)

    const int cg  = tid >> 6;           // channel group (PPG pairs)
    const int sl  = tid & 63;           // pixel slot
    const int py  = sl >> 3;            // tile row 0..7
    const int x0  = (sl & 7) * 4;       // tile col start

    // ---- prefetch input group A (ic 0..7) into regs: 8c x 10row x 34col --
    float pf[11];
#pragma unroll
    for (int j = 0; j < 11; ++j) {
        int idx = tid + j*256;
        float v = 0.f;
        if (idx < 2720) {
            int c   = idx / 340;
            int rem = idx - c*340;
            int yy  = rem / 34;
            int xx  = rem - yy*34;
            int gh  = th0 + yy - 1;
            int gw  = tw0 + xx - 1;
            if (gh >= 0 && gh < 128 && gw >= 0 && gw < 128)
                v = x[((size_t)bt*16 + c)*HW + gh*128 + gw];
        }
        pf[j] = v;
    }

    // ---- stage weights (hides group A LDG latency) ----
    {
        const float* wsrc[3] = {w0, w1, w2};
        for (int idx = tid; idx < NPAIR*144; idx += 256) {
            int pair = idx / 144;
            int r    = idx - pair*144;          // ic*9 + j
            int chA  = pair*2, chB = chA + 1;
            float a  = wsrc[chA >> 4][(chA & 15)*144 + r];
            float b  = wsrc[chB >> 4][(chB & 15)*144 + r];
            int ic   = r / 9;
            int j    = r - ic*9;
            s_w2[(pair*16 + ic)*10 + j] = pk2(a, b);
        }
        for (int idx = tid; idx < NCONV*16; idx += 256) {
            float bv;
            if (NCONV == 3) bv = (idx < 16) ? b0[idx] : (idx < 32 ? b1[idx-16] : b2[idx-32]);
            else            bv = b0[idx];
            s_b[idx] = bv;
        }
    }

    // ---- store group A to smem ----
#pragma unroll
    for (int j = 0; j < 11; ++j) {
        int idx = tid + j*256;
        if (idx < 2720) {
            int c   = idx / 340;
            int rem = idx - c*340;
            int yy  = rem / 34;
            int xx  = rem - yy*34;
            s_in[c*350 + yy*35 + xx] = pf[j];
        }
    }
    __syncthreads();

    // ---- prefetch input group B (ic 8..15); latency hides under compute A
#pragma unroll
    for (int j = 0; j < 11; ++j) {
        int idx = tid + j*256;
        float v = 0.f;
        if (idx < 2720) {
            int c   = idx / 340;            // local 0..7 -> ic 8..15
            int rem = idx - c*340;
            int yy  = rem / 34;
            int xx  = rem - yy*34;
            int gh  = th0 + yy - 1;
            int gw  = tw0 + xx - 1;
            if (gh >= 0 && gh < 128 && gw >= 0 && gw < 128)
                v = x[((size_t)bt*16 + (8 + c))*HW + gh*128 + gw];
        }
        pf[j] = v;
    }

    ull acc[PPG][4];
#pragma unroll
    for (int c = 0; c < PPG; ++c) {
        int q = cg*PPG + c;
        ull b2 = pk2(s_b[2*q], s_b[2*q + 1]);
#pragma unroll
        for (int p = 0; p < 4; ++p) acc[c][p] = b2;
    }

    // ---- compute halves: ic 0..7 (then store B, sync), ic 8..15 ----
#pragma unroll 1
    for (int half = 0; half < 2; ++half) {
        const int iclo = half*8;
        for (int ic = iclo; ic < iclo + 8; ++ic) {
            const float* base = s_in + ic*350 + py*35 + x0;   // rows py..py+2
            ull pkk[3][6];
#pragma unroll
            for (int ky = 0; ky < 3; ++ky)
#pragma unroll
                for (int j = 0; j < 6; ++j) {
                    float v = base[ky*35 + j];
                    pkk[ky][j] = pk2(v, v);
                }
#pragma unroll
            for (int c = 0; c < PPG; ++c) {
                const ull* wp = s_w2 + ((cg*PPG + c)*16 + ic)*10;
                ulonglong2 wA = *(const ulonglong2*)wp;        // taps 0,1
                ulonglong2 wB = *(const ulonglong2*)(wp + 2);  // taps 2,3
                ulonglong2 wC = *(const ulonglong2*)(wp + 4);  // taps 4,5
                ulonglong2 wD = *(const ulonglong2*)(wp + 6);  // taps 6,7
                ull w8 = wp[8];
#pragma unroll
                for (int px = 0; px < 4; ++px) {
                    ull a = acc[c][px];
                    fma2(a, pkk[0][px+0], wA.x);
                    fma2(a, pkk[0][px+1], wA.y);
                    fma2(a, pkk[0][px+2], wB.x);
                    fma2(a, pkk[1][px+0], wB.y);
                    fma2(a, pkk[1][px+1], wC.x);
                    fma2(a, pkk[1][px+2], wC.y);
                    fma2(a, pkk[2][px+0], wD.x);
                    fma2(a, pkk[2][px+1], wD.y);
                    fma2(a, pkk[2][px+2], w8);
                    acc[c][px] = a;
                }
            }
        }
        if (half == 0) {
            // store group B, make visible
#pragma unroll
            for (int j = 0; j < 11; ++j) {
                int idx = tid + j*256;
                if (idx < 2720) {
                    int c   = idx / 340;
                    int rem = idx - c*340;
                    int yy  = rem / 34;
                    int xx  = rem - yy*34;
                    s_in[(8 + c)*350 + yy*35 + xx] = pf[j];
                }
            }
            __syncthreads();
        }
    }

    const int oh = th0 + py;
    const int ow = tw0 + x0;
#pragma unroll
    for (int c = 0; c < PPG; ++c) {
        int q2   = cg*PPG + c;
        int chA  = 2*q2;                 // even; pair never straddles convs
        int conv = chA >> 4;
        int ocA  = chA & 15;
        size_t offA = ((size_t)bt*16 + ocA)*HW + oh*128 + ow;
        size_t offB = offA + HW;
        float2 v0 = upk(acc[c][0]);
        float2 v1 = upk(acc[c][1]);
        float2 v2 = upk(acc[c][2]);
        float2 v3 = upk(acc[c][3]);
        if (NCONV == 1) {
            *(float4*)(out_final + offA) = make_float4(v0.x, v1.x, v2.x, v3.x);
            *(float4*)(out_final + offB) = make_float4(v0.y, v1.y, v2.y, v3.y);
        } else if (conv == 2) {          // v: fp32
            *(float4*)(g_v + offA) = make_float4(v0.x, v1.x, v2.x, v3.x);
            *(float4*)(g_v + offB) = make_float4(v0.y, v1.y, v2.y, v3.y);
        } else {                          // q or k: bf16
            __nv_bfloat16* dst = (conv == 0) ? g_qh : g_kh;
            __nv_bfloat162 a0 = __floats2bfloat162_rn(v0.x, v1.x);
            __nv_bfloat162 a1 = __floats2bfloat162_rn(v2.x, v3.x);
            __nv_bfloat162 b0p = __floats2bfloat162_rn(v0.y, v1.y);
            __nv_bfloat162 b1p = __floats2bfloat162_rn(v2.y, v3.y);
            uint2 uA, uB;
            uA.x = *(unsigned*)&a0;  uA.y = *(unsigned*)&a1;
            uB.x = *(unsigned*)&b0p; uB.y = *(unsigned*)&b1p;
            *(uint2*)(dst + offA) = uA;
            *(uint2*)(dst + offB) = uB;
        }
    }
}

// ---------------- QK^T: 2-stage pipelined staging, FFMA2 inner -----------
// 32 splits x 1024 K-elems each (16 subs of 64).
__global__ void __launch_bounds__(256, 3) qk_kernel()
{
    extern __shared__ float sm[];       // stage stride 8704 floats
    const int bh = blockIdx.y;
    const int b  = bh >> 3, h = bh & 7;
    const int split = blockIdx.x;
    const int tid = threadIdx.x;
    const int ty = tid >> 4, tx = tid & 15;

    int st_t[4], st_kq[4];
#pragma unroll
    for (int j = 0; j < 4; ++j) {
        int i = tid + j*256;
        st_t[j]  = i >> 4;
        st_kq[j] = (i & 15) << 2;
    }

    uint2 qr[4], kr[4];
    {
        const int kc = split*1024;
#pragma unroll
        for (int j = 0; j < 4; ++j) {
            size_t base = ((size_t)((b*64 + st_t[j])*16 + h*2))*HW + kc + st_kq[j];
            qr[j] = *(const uint2*)(g_qh + base);
            kr[j] = *(const uint2*)(g_kh + base);
        }
    }

    ull acc2[4][2];
#pragma unroll
    for (int i = 0; i < 4; ++i) { acc2[i][0] = 0ULL; acc2[i][1] = 0ULL; }

    for (int sub = 0; sub < QK_SUBS; ++sub) {
        float* Qs = sm + (sub & 1)*8704;
        float* Ks = Qs + 4352;
        __syncthreads();
#pragma unroll
        for (int j = 0; j < 4; ++j) {
            float2 q01 = __bfloat1622float2(*(const __nv_bfloat162*)&qr[j].x);
            float2 q23 = __bfloat1622float2(*(const __nv_bfloat162*)&qr[j].y);
            float2 k01 = __bfloat1622float2(*(const __nv_bfloat162*)&kr[j].x);
            float2 k23 = __bfloat1622float2(*(const __nv_bfloat162*)&kr[j].y);
            int t = st_t[j], kq = st_kq[j];
            Qs[(kq+0)*68 + t] = q01.x; Qs[(kq+1)*68 + t] = q01.y;
            Qs[(kq+2)*68 + t] = q23.x; Qs[(kq+3)*68 + t] = q23.y;
            Ks[(kq+0)*68 + t] = k01.x; Ks[(kq+1)*68 + t] = k01.y;
            Ks[(kq+2)*68 + t] = k23.x; Ks[(kq+3)*68 + t] = k23.y;
        }
        if (sub < QK_SUBS - 1) {
            const int kc = split*1024 + (sub+1)*64;
#pragma unroll
            for (int j = 0; j < 4; ++j) {
                size_t base = ((size_t)((b*64 + st_t[j])*16 + h*2))*HW + kc + st_kq[j];
                qr[j] = *(const uint2*)(g_qh + base);
                kr[j] = *(const uint2*)(g_kh + base);
            }
        }
        __syncthreads();
#pragma unroll 8
        for (int kk = 0; kk < 64; ++kk) {
            float4 a = *(const float4*)(Qs + kk*68 + ty*4);
            ulonglong2 bp = *(const ulonglong2*)(Ks + kk*68 + tx*4);
            ull a0 = pk2(a.x, a.x);
            ull a1 = pk2(a.y, a.y);
            ull a2 = pk2(a.z, a.z);
            ull a3 = pk2(a.w, a.w);
            fma2(acc2[0][0], a0, bp.x); fma2(acc2[0][1], a0, bp.y);
            fma2(acc2[1][0], a1, bp.x); fma2(acc2[1][1], a1, bp.y);
            fma2(acc2[2][0], a2, bp.x); fma2(acc2[2][1], a2, bp.y);
            fma2(acc2[3][0], a3, bp.x); fma2(acc2[3][1], a3, bp.y);
        }
    }

    float* dst = g_part + ((size_t)(split*16 + bh))*4096;
#pragma unroll
    for (int i = 0; i < 4; ++i) {
        float2 lo = upk(acc2[i][0]);
        float2 hi = upk(acc2[i][1]);
        *(float4*)(dst + (ty*4 + i)*64 + tx*4) = make_float4(lo.x, lo.y, hi.x, hi.y);
    }
}

// ---------------- split-reduce + causal softmax ----------------
__global__ void softmax_kernel()
{
    const int bh = blockIdx.y;
    const int t  = blockIdx.x;
    const int s  = threadIdx.x;

    float ssum = 0.f;
    for (int sp = 0; sp < QK_SPLITS; ++sp)
        ssum += g_part[((size_t)(sp*16 + bh)*64 + t)*64 + s];

    const float scale = rsqrtf(32768.0f);
    const bool valid = (s <= t);
    float logit = valid ? ssum * scale : -INFINITY;

    __shared__ float red[64];
    red[s] = logit;
    __syncthreads();
    for (int off = 32; off > 0; off >>= 1) {
        if (s < off) red[s] = fmaxf(red[s], red[s + off]);
        __syncthreads();
    }
    float mx = red[0];
    __syncthreads();
    float e = valid ? expf(logit - mx) : 0.f;
    red[s] = e;
    __syncthreads();
    for (int off = 32; off > 0; off >>= 1) {
        if (s < off) red[s] += red[s + off];
        __syncthreads();
    }
    float p = e / red[0];
    g_att[(bh*64 + s)*64 + t] = p;   // 0 for s > t
}

// ---------------- y = att @ V: 2 d/thread, MLP=4 v batching ---------------
__global__ void __launch_bounds__(256, 2) av_kernel()
{
    __shared__ __align__(16) float sa[64][32];   // att[s][t0+tt]
    const int bh = blockIdx.z;
    const int b  = bh >> 3, h = bh & 7;
    const int thalf = blockIdx.y;
    const int t0 = thalf * 32;
    const int smax = thalf ? 64 : 32;   // causal: lower t-half only needs s<32
    const int d0 = blockIdx.x*512 + threadIdx.x*2;

    for (int i = threadIdx.x; i < smax*8; i += 256) {
        int s = i >> 3; int tg = i & 7;
        *(float4*)&sa[s][tg*4] = *(const float4*)(g_att + (bh*64 + s)*64 + t0 + tg*4);
    }
    __syncthreads();

    ull acc[16][2];
#pragma unroll
    for (int g = 0; g < 16; ++g) { acc[g][0] = 0ULL; acc[g][1] = 0ULL; }

    const size_t vbase = ((size_t)(b*64*16 + h*2))*HW + d0;
    for (int s0 = 0; s0 < smax; s0 += 4) {
        float2 vv[4];
#pragma unroll
        for (int j = 0; j < 4; ++j)                 // 4 outstanding LDG.64
            vv[j] = *(const float2*)(g_v + vbase + (size_t)(s0 + j)*16*HW);
#pragma unroll
        for (int j = 0; j < 4; ++j) {
            ull va = pk2(vv[j].x, vv[j].x);
            ull vb = pk2(vv[j].y, vv[j].y);
            const int s = s0 + j;
#pragma unroll
            for (int g = 0; g < 8; ++g) {
                ulonglong2 ap = *(const ulonglong2*)&sa[s][g*4];
                fma2(acc[g*2+0][0], ap.x, va);
                fma2(acc[g*2+0][1], ap.x, vb);
                fma2(acc[g*2+1][0], ap.y, va);
                fma2(acc[g*2+1][1], ap.y, vb);
            }
        }
    }

#pragma unroll
    for (int g = 0; g < 16; ++g) {
        float2 oA = upk(acc[g][0]);   // d0 column: (t even, t odd)
        float2 oB = upk(acc[g][1]);   // d0+1 column
        int t = t0 + g*2;
        *(float2*)(g_q + ((size_t)((b*64 + t  )*16 + h*2))*HW + d0) = make_float2(oA.x, oB.x);
        *(float2*)(g_q + ((size_t)((b*64 + t+1)*16 + h*2))*HW + d0) = make_float2(oA.y, oB.y);
    }
}

// ---------------- launch ----------------
extern "C" void kernel_launch(void* const* d_in, const int* in_sizes, int n_in,
                              void* d_out, int out_size)
{
    const float* x  = (const float*)d_in[0];
    const float* wq = (const float*)d_in[1];
    const float* bq = (const float*)d_in[2];
    const float* wk = (const float*)d_in[3];
    const float* bk = (const float*)d_in[4];
    const float* wv = (const float*)d_in[5];
    const float* bv = (const float*)d_in[6];
    const float* wo = (const float*)d_in[7];
    const float* bo = (const float*)d_in[8];
    float* out = (float*)d_out;

    const int smem3 = 24*160*8 + 16*350*4 + 48*4;  // 53312 B (4 CTAs/SM)
    const int smem1 = 8*160*8  + 16*350*4 + 16*4;  // 32704 B
    const int smemQK = 2 * 2 * 4352 * 4;           // 69632 B
    cudaFuncSetAttribute(conv3x3_kernel<3>, cudaFuncAttributeMaxDynamicSharedMemorySize, smem3);
    cudaFuncSetAttribute(conv3x3_kernel<1>, cudaFuncAttributeMaxDynamicSharedMemorySize, smem1);
    cudaFuncSetAttribute(qk_kernel, cudaFuncAttributeMaxDynamicSharedMemorySize, smemQK);

    dim3 cgrid(64, 128);   // 64 tiles (32x8) x 128 images
    conv3x3_kernel<3><<<cgrid, 256, smem3>>>(x, wq, bq, wk, bk, wv, bv, nullptr);
    qk_kernel<<<dim3(QK_SPLITS, 16), 256, smemQK>>>();
    softmax_kernel<<<dim3(64, 16), 64>>>();
    av_kernel<<<dim3(64, 2, 16), 256>>>();
    conv3x3_kernel<1><<<cgrid, 256, smem1>>>(nullptr, wo, bo, nullptr, nullptr,
                                             nullptr, nullptr, out);
}

// round 15
// speedup vs baseline: 1.0690x; 1.0690x over previous
#include <cstdint>
#include <cuda_runtime.h>
#include <cuda_bf16.h>
#include <math.h>

// x: [B=2, T=64, C=16, H=128, W=128] f32; qkv conv 3x3 pad1 (16->16),
// nh=8, hc=2, D=32768; causal softmax T=64; out conv 3x3 (16->16).
#define HW 16384
typedef unsigned long long ull;

// ---------------- packed fp32x2 helpers (FFMA2 path) ----------------------
__device__ __forceinline__ ull pk2(float lo, float hi) {
    ull r;
    asm("mov.b64 %0, {%1, %2};"
        : "=l"(r) : "r"(__float_as_uint(lo)), "r"(__float_as_uint(hi)));
    return r;
}
__device__ __forceinline__ void fma2(ull& d, ull a, ull b) {
    asm("fma.rn.f32x2 %0, %1, %2, %0;" : "+l"(d) : "l"(a), "l"(b));
}
__device__ __forceinline__ float2 upk(ull v) {
    unsigned lo, hi;
    asm("mov.b64 {%0, %1}, %2;" : "=r"(lo), "=r"(hi) : "l"(v));
    return make_float2(__uint_as_float(lo), __uint_as_float(hi));
}

// ---------------- scratch ----------------
__device__ float         g_q[2*64*16*16384];   // y (attention output)
__device__ float         g_v[2*64*16*16384];   // v (fp32: precision-critical)
__device__ __nv_bfloat16 g_qh[2*64*16*16384];  // q bf16
__device__ __nv_bfloat16 g_kh[2*64*16*16384];  // k bf16
__device__ float g_part[64*16*64*64];          // QK^T partials per k-split
__device__ float g_att[16*64*64];              // softmax probs, [bh][s][t]

// ================= Q,K conv via warp-level bf16 mma.sync ==================
// Block = (image bt, row h): D[128 px][32 oc] = sum over 9 taps of
// A_ky[128 px][16 ic] @ B_kykx[32 oc][16 ic]^T, A columns pack kx shifts
// at kx*16+ic (value x[ic][h+ky-1][px-1+kx]).  4 warps, warp w owns px rows
// w*32..w*32+31 (2 m16 tiles) x all 4 n8 tiles, 9 K=16 steps.
// smem: A bf16 [3][128][56] @ 0 (43008B), B bf16 [9][32][16] @ 43008 (9216B),
// bias f32[32] @ 52224.  Epilogue: D -> smem f32 [32][130] (reuses A) ->
// coalesced bf16x2 global stores.
#define MA(ky)   ((ky)*14336)
#define MBOFF    43008
#define MBIAS    52224
#define MSMEM    52352

__device__ __forceinline__ void mma16816(float* c, unsigned a0, unsigned a1,
                                         unsigned a2, unsigned a3,
                                         unsigned b0, unsigned b1) {
    asm volatile(
        "mma.sync.aligned.m16n8k16.row.col.f32.bf16.bf16.f32 "
        "{%0,%1,%2,%3}, {%4,%5,%6,%7}, {%8,%9}, {%0,%1,%2,%3};"
        : "+f"(c[0]), "+f"(c[1]), "+f"(c[2]), "+f"(c[3])
        : "r"(a0), "r"(a1), "r"(a2), "r"(a3), "r"(b0), "r"(b1));
}

__global__ void __launch_bounds__(128)
qkconv_mma_kernel(const float* __restrict__ x,
                  const float* __restrict__ wq, const float* __restrict__ bq,
                  const float* __restrict__ wk, const float* __restrict__ bk)
{
    extern __shared__ char sm[];
    const int tid = threadIdx.x;
    const int h  = blockIdx.x;
    const int bt = blockIdx.y;

    // ---- stage A: thread = (ic pair, 8-px group), same pattern as R13 ----
    {
        const int icp = tid & 7, pg = tid >> 3;
        const int ic0 = icp*2;
        for (int ky = 0; ky < 3; ++ky) {
            const int r = h + ky - 1;
            const bool rok = (r >= 0) && (r < 128);
            const float* xr0 = x + ((size_t)bt*16 + ic0)*HW + r*128;
#pragma unroll
            for (int j = 0; j < 10; ++j) {          // p = pg*8-1 .. pg*8+8
                int p = pg*8 + j - 1;
                if (j == 0 && pg != 0) continue;     // p=-1 only via pg0
                if (j == 9 && pg != 15) continue;    // p=128 only via pg15
                float v0 = 0.f, v1 = 0.f;
                if (rok && p >= 0 && p < 128) { v0 = xr0[p]; v1 = xr0[p + HW]; }
                __nv_bfloat162 bb = __floats2bfloat162_rn(v0, v1);
                unsigned u = *(unsigned*)&bb;
#pragma unroll
                for (int kx = 0; kx < 3; ++kx) {
                    int m = p + 1 - kx;
                    if (m >= 0 && m < 128)
                        *(unsigned*)(sm + MA(ky) + (m*56 + kx*16 + ic0)*2) = u;
                }
            }
        }
    }

    // ---- stage B: [kyx][oc][16 ic] bf16, 2304 u32 words ----
    for (int idx = tid; idx < 2304; idx += 128) {
        int kyx = idx >> 8;            // ky*3+kx
        int rem = idx & 255;
        int oc  = rem >> 3;
        int ic  = (rem & 7)*2;
        int ky  = kyx/3, kx = kyx - ky*3;
        const float* ws = (oc < 16) ? wq : wk;
        int o16 = oc & 15;
        float a = ws[o16*144 + ic*9     + ky*3 + kx];
        float b = ws[o16*144 + (ic+1)*9 + ky*3 + kx];
        __nv_bfloat162 bb = __floats2bfloat162_rn(a, b);
        *(unsigned*)(sm + MBOFF + ((kyx*32 + oc)*16 + ic)*2) = *(unsigned*)&bb;
    }
    if (tid < 32)
        ((float*)(sm + MBIAS))[tid] = (tid < 16) ? bq[tid] : bk[tid - 16];
    __syncthreads();

    // ---- 9 accumulated K=16 MMA steps ----
    const int w = tid >> 5, lane = tid & 31;
    const int g = lane >> 2, t = lane & 3;
    float acc[2][4][4];
#pragma unroll
    for (int mt = 0; mt < 2; ++mt)
#pragma unroll
        for (int nt = 0; nt < 4; ++nt)
#pragma unroll
            for (int i = 0; i < 4; ++i) acc[mt][nt][i] = 0.f;

#pragma unroll
    for (int kyx = 0; kyx < 9; ++kyx) {
        const int ky = kyx/3, kx = kyx - ky*3;
        const char* Ab = sm + MA(ky);
        const int colb = kx*16 + t*2;
        unsigned a[2][4];
#pragma unroll
        for (int mt = 0; mt < 2; ++mt) {
            int row0 = w*32 + mt*16 + g;
            a[mt][0] = *(const unsigned*)(Ab + ( row0     *56 + colb    )*2);
            a[mt][1] = *(const unsigned*)(Ab + ((row0 + 8)*56 + colb    )*2);
            a[mt][2] = *(const unsigned*)(Ab + ( row0     *56 + colb + 8)*2);
            a[mt][3] = *(const unsigned*)(Ab + ((row0 + 8)*56 + colb + 8)*2);
        }
        const char* Bb = sm + MBOFF + kyx*1024;    // 32*16*2
#pragma unroll
        for (int nt = 0; nt < 4; ++nt) {
            int oc = nt*8 + g;
            unsigned b0 = *(const unsigned*)(Bb + (oc*16 + t*2    )*2);
            unsigned b1 = *(const unsigned*)(Bb + (oc*16 + t*2 + 8)*2);
            mma16816(acc[0][nt], a[0][0], a[0][1], a[0][2], a[0][3], b0, b1);
            mma16816(acc[1][nt], a[1][0], a[1][1], a[1][2], a[1][3], b0, b1);
        }
    }

    // ---- transpose D through smem (reuses A region), then coalesced out --
    __syncthreads();
    float* Dt = (float*)sm;                         // [32 oc][130]
#pragma unroll
    for (int mt = 0; mt < 2; ++mt) {
        int row0 = w*32 + mt*16 + g;
#pragma unroll
        for (int nt = 0; nt < 4; ++nt) {
            int col0 = nt*8 + t*2;
            Dt[ col0     *130 + row0    ] = acc[mt][nt][0];
            Dt[(col0 + 1)*130 + row0    ] = acc[mt][nt][1];
            Dt[ col0     *130 + row0 + 8] = acc[mt][nt][2];
            Dt[(col0 + 1)*130 + row0 + 8] = acc[mt][nt][3];
        }
    }
    __syncthreads();

    const float* sb = (const float*)(sm + MBIAS);
    for (int i = tid; i < 2048; i += 128) {         // 32 oc x 64 px-pairs
        int oc = i >> 6;
        int px = (i & 63)*2;
        float bias = sb[oc];
        float v0 = Dt[oc*130 + px]     + bias;
        float v1 = Dt[oc*130 + px + 1] + bias;
        __nv_bfloat162 bb = __floats2bfloat162_rn(v0, v1);
        __nv_bfloat16* dst = (oc < 16) ? g_qh : g_kh;
        *(unsigned*)(dst + ((size_t)bt*16 + (oc & 15))*HW + h*128 + px) =
            *(unsigned*)&bb;
    }
}

// ================= 3x3 conv FFMA2 (proven R11 variant), single conv =======
// TOV=true: v-conv (x -> g_v fp32); TOV=false: out-conv (g_q -> out fp32).
template<bool TOV>
__global__ void __launch_bounds__(128) conv3x3_kernel(
    const float* __restrict__ xin,
    const float* __restrict__ w0, const float* __restrict__ b0,
    float* __restrict__ out_final)
{
    extern __shared__ ull dyn[];
    ull*   s_w2 = dyn;                          // 8 pairs * 16ic * 10
    float* s_in = (float*)(dyn + 8*160);        // 16c x 6row x 35 halo tile
    float* s_b  = s_in + 16*210;                // 16 biases

    const int tid = threadIdx.x;
    const int bt  = blockIdx.y;
    const int th0 = (blockIdx.x >> 2) * 4;
    const int tw0 = (blockIdx.x & 3) * 32;

    const float* x = TOV ? xin : g_q;

    const int cg  = tid >> 5;
    const int sl  = tid & 31;
    const int py  = sl >> 3;
    const int x0  = (sl & 7) * 4;

    // prefetch input group A (ic 0..7)
    float pf[13];
#pragma unroll
    for (int j = 0; j < 13; ++j) {
        int idx = tid + j*128;
        float v = 0.f;
        if (idx < 1632) {
            int c   = idx / 204;
            int rem = idx - c*204;
            int yy  = rem / 34;
            int xx  = rem - yy*34;
            int gh  = th0 + yy - 1;
            int gw  = tw0 + xx - 1;
            if (gh >= 0 && gh < 128 && gw >= 0 && gw < 128)
                v = x[((size_t)bt*16 + c)*HW + gh*128 + gw];
        }
        pf[j] = v;
    }

    // stage weights (hides group A latency)
    for (int idx = tid; idx < 8*144; idx += 128) {
        int pair = idx / 144;
        int r    = idx - pair*144;
        int chA  = pair*2;
        float a  = w0[chA*144 + r];
        float b  = w0[(chA+1)*144 + r];
        int ic   = r / 9;
        int j    = r - ic*9;
        s_w2[(pair*16 + ic)*10 + j] = pk2(a, b);
    }
    if (tid < 16) s_b[tid] = b0[tid];

    // store group A
#pragma unroll
    for (int j = 0; j < 13; ++j) {
        int idx = tid + j*128;
        if (idx < 1632) {
            int c   = idx / 204;
            int rem = idx - c*204;
            int yy  = rem / 34;
            int xx  = rem - yy*34;
            s_in[c*210 + yy*35 + xx] = pf[j];
        }
    }
    __syncthreads();

    // prefetch group B (ic 8..15)
#pragma unroll
    for (int j = 0; j < 13; ++j) {
        int idx = tid + j*128;
        float v = 0.f;
        if (idx < 1632) {
            int c   = 8 + idx / 204;
            int rem = idx - (c - 8)*204;
            int yy  = rem / 34;
            int xx  = rem - yy*34;
            int gh  = th0 + yy - 1;
            int gw  = tw0 + xx - 1;
            if (gh >= 0 && gh < 128 && gw >= 0 && gw < 128)
                v = x[((size_t)bt*16 + c)*HW + gh*128 + gw];
        }
        pf[j] = v;
    }

    ull acc[2][4];
#pragma unroll
    for (int c = 0; c < 2; ++c) {
        int q = cg*2 + c;
        ull b2 = pk2(s_b[2*q], s_b[2*q + 1]);
#pragma unroll
        for (int p = 0; p < 4; ++p) acc[c][p] = b2;
    }

#pragma unroll 1
    for (int half = 0; half < 2; ++half) {
        const int iclo = half*8;
        for (int ic = iclo; ic < iclo + 8; ++ic) {
            const float* base = s_in + ic*210 + py*35 + x0;
            ull pkk[3][6];
#pragma unroll
            for (int ky = 0; ky < 3; ++ky)
#pragma unroll
                for (int j = 0; j < 6; ++j) {
                    float v = base[ky*35 + j];
                    pkk[ky][j] = pk2(v, v);
                }
#pragma unroll
            for (int c = 0; c < 2; ++c) {
                const ull* wp = s_w2 + ((cg*2 + c)*16 + ic)*10;
                ulonglong2 wA = *(const ulonglong2*)wp;
                ulonglong2 wB = *(const ulonglong2*)(wp + 2);
                ulonglong2 wC = *(const ulonglong2*)(wp + 4);
                ulonglong2 wD = *(const ulonglong2*)(wp + 6);
                ull w8 = wp[8];
#pragma unroll
                for (int px = 0; px < 4; ++px) {
                    ull a = acc[c][px];
                    fma2(a, pkk[0][px+0], wA.x);
                    fma2(a, pkk[0][px+1], wA.y);
                    fma2(a, pkk[0][px+2], wB.x);
                    fma2(a, pkk[1][px+0], wB.y);
                    fma2(a, pkk[1][px+1], wC.x);
                    fma2(a, pkk[1][px+2], wC.y);
                    fma2(a, pkk[2][px+0], wD.x);
                    fma2(a, pkk[2][px+1], wD.y);
                    fma2(a, pkk[2][px+2], w8);
                    acc[c][px] = a;
                }
            }
        }
        if (half == 0) {
#pragma unroll
            for (int j = 0; j < 13; ++j) {
                int idx = tid + j*128;
                if (idx < 1632) {
                    int c   = 8 + idx / 204;
                    int rem = idx - (c - 8)*204;
                    int yy  = rem / 34;
                    int xx  = rem - yy*34;
                    s_in[c*210 + yy*35 + xx] = pf[j];
                }
            }
            __syncthreads();
        }
    }

    const int oh = th0 + py;
    const int ow = tw0 + x0;
    float* outp = TOV ? g_v : out_final;
#pragma unroll
    for (int c = 0; c < 2; ++c) {
        int chA = (cg*2 + c)*2;
        size_t offA = ((size_t)bt*16 + chA)*HW + oh*128 + ow;
        float2 v0 = upk(acc[c][0]);
        float2 v1 = upk(acc[c][1]);
        float2 v2 = upk(acc[c][2]);
        float2 v3 = upk(acc[c][3]);
        *(float4*)(outp + offA)      = make_float4(v0.x, v1.x, v2.x, v3.x);
        *(float4*)(outp + offA + HW) = make_float4(v0.y, v1.y, v2.y, v3.y);
    }
}

// ---------------- QK^T: 2-stage pipelined staging, FFMA2 inner -----------
__global__ void __launch_bounds__(256, 3) qk_kernel()
{
    extern __shared__ float smf[];      // stage stride 8704 floats
    const int bh = blockIdx.y;
    const int b  = bh >> 3, h = bh & 7;
    const int split = blockIdx.x;
    const int tid = threadIdx.x;
    const int ty = tid >> 4, tx = tid & 15;

    int st_t[4], st_kq[4];
#pragma unroll
    for (int j = 0; j < 4; ++j) {
        int i = tid + j*256;
        st_t[j]  = i >> 4;
        st_kq[j] = (i & 15) << 2;
    }

    uint2 qr[4], kr[4];
    {
        const int kc = split*512;
#pragma unroll
        for (int j = 0; j < 4; ++j) {
            size_t base = ((size_t)((b*64 + st_t[j])*16 + h*2))*HW + kc + st_kq[j];
            qr[j] = *(const uint2*)(g_qh + base);
            kr[j] = *(const uint2*)(g_kh + base);
        }
    }

    ull acc2[4][2];
#pragma unroll
    for (int i = 0; i < 4; ++i) { acc2[i][0] = 0ULL; acc2[i][1] = 0ULL; }

    for (int sub = 0; sub < 8; ++sub) {
        float* Qs = smf + (sub & 1)*8704;
        float* Ks = Qs + 4352;
        __syncthreads();
#pragma unroll
        for (int j = 0; j < 4; ++j) {
            float2 q01 = __bfloat1622float2(*(const __nv_bfloat162*)&qr[j].x);
            float2 q23 = __bfloat1622float2(*(const __nv_bfloat162*)&qr[j].y);
            float2 k01 = __bfloat1622float2(*(const __nv_bfloat162*)&kr[j].x);
            float2 k23 = __bfloat1622float2(*(const __nv_bfloat162*)&kr[j].y);
            int t = st_t[j], kq = st_kq[j];
            Qs[(kq+0)*68 + t] = q01.x; Qs[(kq+1)*68 + t] = q01.y;
            Qs[(kq+2)*68 + t] = q23.x; Qs[(kq+3)*68 + t] = q23.y;
            Ks[(kq+0)*68 + t] = k01.x; Ks[(kq+1)*68 + t] = k01.y;
            Ks[(kq+2)*68 + t] = k23.x; Ks[(kq+3)*68 + t] = k23.y;
        }
        if (sub < 7) {
            const int kc = split*512 + (sub+1)*64;
#pragma unroll
            for (int j = 0; j < 4; ++j) {
                size_t base = ((size_t)((b*64 + st_t[j])*16 + h*2))*HW + kc + st_kq[j];
                qr[j] = *(const uint2*)(g_qh + base);
                kr[j] = *(const uint2*)(g_kh + base);
            }
        }
        __syncthreads();
#pragma unroll 8
        for (int kk = 0; kk < 64; ++kk) {
            float4 a = *(const float4*)(Qs + kk*68 + ty*4);
            ulonglong2 bp = *(const ulonglong2*)(Ks + kk*68 + tx*4);
            ull a0 = pk2(a.x, a.x);
            ull a1 = pk2(a.y, a.y);
            ull a2 = pk2(a.z, a.z);
            ull a3 = pk2(a.w, a.w);
            fma2(acc2[0][0], a0, bp.x); fma2(acc2[0][1], a0, bp.y);
            fma2(acc2[1][0], a1, bp.x); fma2(acc2[1][1], a1, bp.y);
            fma2(acc2[2][0], a2, bp.x); fma2(acc2[2][1], a2, bp.y);
            fma2(acc2[3][0], a3, bp.x); fma2(acc2[3][1], a3, bp.y);
        }
    }

    float* dst = g_part + ((size_t)(split*16 + bh))*4096;
#pragma unroll
    for (int i = 0; i < 4; ++i) {
        float2 lo = upk(acc2[i][0]);
        float2 hi = upk(acc2[i][1]);
        *(float4*)(dst + (ty*4 + i)*64 + tx*4) = make_float4(lo.x, lo.y, hi.x, hi.y);
    }
}

// ---------------- split-reduce + causal softmax ----------------
__global__ void softmax_kernel()
{
    const int bh = blockIdx.y;
    const int t  = blockIdx.x;
    const int s  = threadIdx.x;

    float ssum = 0.f;
    for (int sp = 0; sp < 64; ++sp)
        ssum += g_part[((size_t)(sp*16 + bh)*64 + t)*64 + s];

    const float scale = rsqrtf(32768.0f);
    const bool valid = (s <= t);
    float logit = valid ? ssum * scale : -INFINITY;

    __shared__ float red[64];
    red[s] = logit;
    __syncthreads();
    for (int off = 32; off > 0; off >>= 1) {
        if (s < off) red[s] = fmaxf(red[s], red[s + off]);
        __syncthreads();
    }
    float mx = red[0];
    __syncthreads();
    float e = valid ? expf(logit - mx) : 0.f;
    red[s] = e;
    __syncthreads();
    for (int off = 32; off > 0; off >>= 1) {
        if (s < off) red[s] += red[s + off];
        __syncthreads();
    }
    float p = e / red[0];
    g_att[(bh*64 + s)*64 + t] = p;   // 0 for s > t
}

// ---------------- y = att @ V: 2 d/thread, MLP=4 v batching ---------------
__global__ void __launch_bounds__(256, 2) av_kernel()
{
    __shared__ __align__(16) float sa[64][32];
    const int bh = blockIdx.z;
    const int b  = bh >> 3, h = bh & 7;
    const int thalf = blockIdx.y;
    const int t0 = thalf * 32;
    const int smax = thalf ? 64 : 32;
    const int d0 = blockIdx.x*512 + threadIdx.x*2;

    for (int i = threadIdx.x; i < smax*8; i += 256) {
        int s = i >> 3; int tg = i & 7;
        *(float4*)&sa[s][tg*4] = *(const float4*)(g_att + (bh*64 + s)*64 + t0 + tg*4);
    }
    __syncthreads();

    ull acc[16][2];
#pragma unroll
    for (int g = 0; g < 16; ++g) { acc[g][0] = 0ULL; acc[g][1] = 0ULL; }

    const size_t vbase = ((size_t)(b*64*16 + h*2))*HW + d0;
    for (int s0 = 0; s0 < smax; s0 += 4) {
        float2 vv[4];
#pragma unroll
        for (int j = 0; j < 4; ++j)
            vv[j] = *(const float2*)(g_v + vbase + (size_t)(s0 + j)*16*HW);
#pragma unroll
        for (int j = 0; j < 4; ++j) {
            ull va = pk2(vv[j].x, vv[j].x);
            ull vb = pk2(vv[j].y, vv[j].y);
            const int s = s0 + j;
#pragma unroll
            for (int g = 0; g < 8; ++g) {
                ulonglong2 ap = *(const ulonglong2*)&sa[s][g*4];
                fma2(acc[g*2+0][0], ap.x, va);
                fma2(acc[g*2+0][1], ap.x, vb);
                fma2(acc[g*2+1][0], ap.y, va);
                fma2(acc[g*2+1][1], ap.y, vb);
            }
        }
    }

#pragma unroll
    for (int g = 0; g < 16; ++g) {
        float2 oA = upk(acc[g][0]);
        float2 oB = upk(acc[g][1]);
        int t = t0 + g*2;
        *(float2*)(g_q + ((size_t)((b*64 + t  )*16 + h*2))*HW + d0) = make_float2(oA.x, oB.x);
        *(float2*)(g_q + ((size_t)((b*64 + t+1)*16 + h*2))*HW + d0) = make_float2(oA.y, oB.y);
    }
}

// ---------------- launch ----------------
extern "C" void kernel_launch(void* const* d_in, const int* in_sizes, int n_in,
                              void* d_out, int out_size)
{
    const float* x  = (const float*)d_in[0];
    const float* wq = (const float*)d_in[1];
    const float* bq = (const float*)d_in[2];
    const float* wk = (const float*)d_in[3];
    const float* bk = (const float*)d_in[4];
    const float* wv = (const float*)d_in[5];
    const float* bv = (const float*)d_in[6];
    const float* wo = (const float*)d_in[7];
    const float* bo = (const float*)d_in[8];
    float* out = (float*)d_out;

    const int smemC  = 8*160*8 + 16*210*4 + 16*4;  // 23744 B
    const int smemQK = 2 * 2 * 4352 * 4;           // 69632 B
    cudaFuncSetAttribute(qkconv_mma_kernel, cudaFuncAttributeMaxDynamicSharedMemorySize, MSMEM);
    cudaFuncSetAttribute(conv3x3_kernel<true>,  cudaFuncAttributeMaxDynamicSharedMemorySize, smemC);
    cudaFuncSetAttribute(conv3x3_kernel<false>, cudaFuncAttributeMaxDynamicSharedMemorySize, smemC);
    cudaFuncSetAttribute(qk_kernel, cudaFuncAttributeMaxDynamicSharedMemorySize, smemQK);

    qkconv_mma_kernel<<<dim3(128, 128), 128, MSMEM>>>(x, wq, bq, wk, bk);
    conv3x3_kernel<true><<<dim3(128, 128), 128, smemC>>>(x, wv, bv, nullptr);
    qk_kernel<<<dim3(64, 16), 256, smemQK>>>();
    softmax_kernel<<<dim3(64, 16), 64>>>();
    av_kernel<<<dim3(64, 2, 16), 256>>>();
    conv3x3_kernel<false><<<dim3(128, 128), 128, smemC>>>(nullptr, wo, bo, out);
}

// round 16
// speedup vs baseline: 1.2458x; 1.1654x over previous
#include <cstdint>
#include <cuda_runtime.h>
#include <cuda_bf16.h>
#include <math.h>

// x: [B=2, T=64, C=16, H=128, W=128] f32; qkv conv 3x3 pad1 (16->16),
// nh=8, hc=2, D=32768; causal softmax T=64; out conv 3x3 (16->16).
#define HW 16384
typedef unsigned long long ull;

// ---------------- packed fp32x2 helpers (FFMA2 path) ----------------------
__device__ __forceinline__ ull pk2(float lo, float hi) {
    ull r;
    asm("mov.b64 %0, {%1, %2};"
        : "=l"(r) : "r"(__float_as_uint(lo)), "r"(__float_as_uint(hi)));
    return r;
}
__device__ __forceinline__ void fma2(ull& d, ull a, ull b) {
    asm("fma.rn.f32x2 %0, %1, %2, %0;" : "+l"(d) : "l"(a), "l"(b));
}
__device__ __forceinline__ float2 upk(ull v) {
    unsigned lo, hi;
    asm("mov.b64 {%0, %1}, %2;" : "=r"(lo), "=r"(hi) : "l"(v));
    return make_float2(__uint_as_float(lo), __uint_as_float(hi));
}

// ---------------- scratch ----------------
__device__ float         g_q[2*64*16*16384];   // y (attention output)
__device__ float         g_v[2*64*16*16384];   // v (fp32: precision-critical)
__device__ __nv_bfloat16 g_qh[2*64*16*16384];  // q bf16
__device__ __nv_bfloat16 g_kh[2*64*16*16384];  // k bf16
__device__ float g_part[64*16*64*64];          // QK^T partials per k-split
__device__ float g_att[16*64*64];              // softmax probs, [bh][s][t]

// ================= Q,K conv via warp-level bf16 mma.sync (v2) =============
// Block = (image bt, row-pair hp): output rows h0=2hp, h0+1.
// A staged ONCE as [4 input rows][132 px][16 ic] bf16 (px index = col+1,
// cols -1..128 valid); tap (ky,kx) for output row rr = A row-tile (rr+ky),
// fragment row m+kx — NO kx duplication in smem.
// Warp w: rr = w>>1, px half = w&1 (64 px = 4 m16 tiles) x 4 n8 tiles.
// smem: A @ 0 (16896B), B [9][32][16] @ 16896 (9216B), bias @ 26112.
#define MAROW    4224                    // 132*16*2 bytes per input-row tile
#define MBOFF    16896
#define MBIAS    26112
#define MSMEM    26240

__device__ __forceinline__ void mma16816(float* c, unsigned a0, unsigned a1,
                                         unsigned a2, unsigned a3,
                                         unsigned b0, unsigned b1) {
    asm volatile(
        "mma.sync.aligned.m16n8k16.row.col.f32.bf16.bf16.f32 "
        "{%0,%1,%2,%3}, {%4,%5,%6,%7}, {%8,%9}, {%0,%1,%2,%3};"
        : "+f"(c[0]), "+f"(c[1]), "+f"(c[2]), "+f"(c[3])
        : "r"(a0), "r"(a1), "r"(a2), "r"(a3), "r"(b0), "r"(b1));
}

__global__ void __launch_bounds__(128)
qkconv_mma_kernel(const float* __restrict__ x,
                  const float* __restrict__ wq, const float* __restrict__ bq,
                  const float* __restrict__ wk, const float* __restrict__ bk)
{
    extern __shared__ char sm[];
    const int tid = threadIdx.x;
    const int h0 = blockIdx.x * 2;
    const int bt = blockIdx.y;

    // ---- stage A: [4 input rows h0-1..h0+2][px+1][16 ic], stored once ----
    {
        const int icp = tid & 7, pg = tid >> 3;
        const int ic0 = icp*2;
        for (int ri = 0; ri < 4; ++ri) {
            const int r = h0 + ri - 1;
            const bool rok = (r >= 0) && (r < 128);
            const float* xr0 = x + ((size_t)bt*16 + ic0)*HW + r*128;
#pragma unroll
            for (int j = 0; j < 10; ++j) {          // p = pg*8-1 .. pg*8+8
                int p = pg*8 + j - 1;
                if (j == 0 && pg != 0) continue;     // p=-1 only via pg0
                if (j == 9 && pg != 15) continue;    // p=128 only via pg15
                float v0 = 0.f, v1 = 0.f;
                if (rok && p >= 0 && p < 128) { v0 = xr0[p]; v1 = xr0[p + HW]; }
                __nv_bfloat162 bb = __floats2bfloat162_rn(v0, v1);
                *(unsigned*)(sm + ri*MAROW + ((p + 1)*16 + ic0)*2) =
                    *(unsigned*)&bb;
            }
        }
    }

    // ---- stage B: [kyx][oc][16 ic] bf16 ----
    for (int idx = tid; idx < 2304; idx += 128) {
        int kyx = idx >> 8;            // ky*3+kx
        int rem = idx & 255;
        int oc  = rem >> 3;
        int ic  = (rem & 7)*2;
        int ky  = kyx/3, kx = kyx - ky*3;
        const float* ws = (oc < 16) ? wq : wk;
        int o16 = oc & 15;
        float a = ws[o16*144 + ic*9     + ky*3 + kx];
        float b = ws[o16*144 + (ic+1)*9 + ky*3 + kx];
        __nv_bfloat162 bb = __floats2bfloat162_rn(a, b);
        *(unsigned*)(sm + MBOFF + ((kyx*32 + oc)*16 + ic)*2) = *(unsigned*)&bb;
    }
    if (tid < 32)
        ((float*)(sm + MBIAS))[tid] = (tid < 16) ? bq[tid] : bk[tid - 16];
    __syncthreads();

    // ---- 9 accumulated K=16 MMA steps ----
    const int w = tid >> 5, lane = tid & 31;
    const int rr = w >> 1, half = w & 1;
    const int g = lane >> 2, t = lane & 3;
    float acc[4][4][4];
#pragma unroll
    for (int mt = 0; mt < 4; ++mt)
#pragma unroll
        for (int nt = 0; nt < 4; ++nt)
#pragma unroll
            for (int i = 0; i < 4; ++i) acc[mt][nt][i] = 0.f;

#pragma unroll
    for (int kyx = 0; kyx < 9; ++kyx) {
        const int ky = kyx/3, kx = kyx - ky*3;
        const char* Ab = sm + (rr + ky)*MAROW;
        unsigned a[4][4];
#pragma unroll
        for (int mt = 0; mt < 4; ++mt) {
            int row0 = half*64 + mt*16 + g + kx;    // A px index m+kx
            a[mt][0] = *(const unsigned*)(Ab + ( row0     *16 + t*2    )*2);
            a[mt][1] = *(const unsigned*)(Ab + ((row0 + 8)*16 + t*2    )*2);
            a[mt][2] = *(const unsigned*)(Ab + ( row0     *16 + t*2 + 8)*2);
            a[mt][3] = *(const unsigned*)(Ab + ((row0 + 8)*16 + t*2 + 8)*2);
        }
        const char* Bb = sm + MBOFF + kyx*1024;     // 32*16*2
#pragma unroll
        for (int nt = 0; nt < 4; ++nt) {
            int oc = nt*8 + g;
            unsigned b0 = *(const unsigned*)(Bb + (oc*16 + t*2    )*2);
            unsigned b1 = *(const unsigned*)(Bb + (oc*16 + t*2 + 8)*2);
#pragma unroll
            for (int mt = 0; mt < 4; ++mt)
                mma16816(acc[mt][nt], a[mt][0], a[mt][1], a[mt][2], a[mt][3],
                         b0, b1);
        }
    }

    // ---- epilogue: one output row at a time through smem (reuses A) ------
    const float* sb = (const float*)(sm + MBIAS);
    float* Dt = (float*)sm;                         // [32 oc][130] f32
#pragma unroll 1
    for (int orow = 0; orow < 2; ++orow) {
        __syncthreads();
        if (rr == orow) {
#pragma unroll
            for (int mt = 0; mt < 4; ++mt) {
                int row0 = half*64 + mt*16 + g;
#pragma unroll
                for (int nt = 0; nt < 4; ++nt) {
                    int col0 = nt*8 + t*2;
                    Dt[ col0     *130 + row0    ] = acc[mt][nt][0];
                    Dt[(col0 + 1)*130 + row0    ] = acc[mt][nt][1];
                    Dt[ col0     *130 + row0 + 8] = acc[mt][nt][2];
                    Dt[(col0 + 1)*130 + row0 + 8] = acc[mt][nt][3];
                }
            }
        }
        __syncthreads();
        const int h = h0 + orow;
        for (int i = tid; i < 2048; i += 128) {     // 32 oc x 64 px-pairs
            int oc = i >> 6;
            int px = (i & 63)*2;
            float bias = sb[oc];
            float v0 = Dt[oc*130 + px]     + bias;
            float v1 = Dt[oc*130 + px + 1] + bias;
            __nv_bfloat162 bb = __floats2bfloat162_rn(v0, v1);
            __nv_bfloat16* dst = (oc < 16) ? g_qh : g_kh;
            *(unsigned*)(dst + ((size_t)bt*16 + (oc & 15))*HW + h*128 + px) =
                *(unsigned*)&bb;
        }
    }
}

// ================= 3x3 conv FFMA2 (proven R11 variant), single conv =======
// TOV=true: v-conv (x -> g_v fp32); TOV=false: out-conv (g_q -> out fp32).
template<bool TOV>
__global__ void __launch_bounds__(128) conv3x3_kernel(
    const float* __restrict__ xin,
    const float* __restrict__ w0, const float* __restrict__ b0,
    float* __restrict__ out_final)
{
    extern __shared__ ull dyn[];
    ull*   s_w2 = dyn;                          // 8 pairs * 16ic * 10
    float* s_in = (float*)(dyn + 8*160);        // 16c x 6row x 35 halo tile
    float* s_b  = s_in + 16*210;                // 16 biases

    const int tid = threadIdx.x;
    const int bt  = blockIdx.y;
    const int th0 = (blockIdx.x >> 2) * 4;
    const int tw0 = (blockIdx.x & 3) * 32;

    const float* x = TOV ? xin : g_q;

    const int cg  = tid >> 5;
    const int sl  = tid & 31;
    const int py  = sl >> 3;
    const int x0  = (sl & 7) * 4;

    // prefetch input group A (ic 0..7)
    float pf[13];
#pragma unroll
    for (int j = 0; j < 13; ++j) {
        int idx = tid + j*128;
        float v = 0.f;
        if (idx < 1632) {
            int c   = idx / 204;
            int rem = idx - c*204;
            int yy  = rem / 34;
            int xx  = rem - yy*34;
            int gh  = th0 + yy - 1;
            int gw  = tw0 + xx - 1;
            if (gh >= 0 && gh < 128 && gw >= 0 && gw < 128)
                v = x[((size_t)bt*16 + c)*HW + gh*128 + gw];
        }
        pf[j] = v;
    }

    // stage weights (hides group A latency)
    for (int idx = tid; idx < 8*144; idx += 128) {
        int pair = idx / 144;
        int r    = idx - pair*144;
        int chA  = pair*2;
        float a  = w0[chA*144 + r];
        float b  = w0[(chA+1)*144 + r];
        int ic   = r / 9;
        int j    = r - ic*9;
        s_w2[(pair*16 + ic)*10 + j] = pk2(a, b);
    }
    if (tid < 16) s_b[tid] = b0[tid];

    // store group A
#pragma unroll
    for (int j = 0; j < 13; ++j) {
        int idx = tid + j*128;
        if (idx < 1632) {
            int c   = idx / 204;
            int rem = idx - c*204;
            int yy  = rem / 34;
            int xx  = rem - yy*34;
            s_in[c*210 + yy*35 + xx] = pf[j];
        }
    }
    __syncthreads();

    // prefetch group B (ic 8..15)
#pragma unroll
    for (int j = 0; j < 13; ++j) {
        int idx = tid + j*128;
        float v = 0.f;
        if (idx < 1632) {
            int c   = 8 + idx / 204;
            int rem = idx - (c - 8)*204;
            int yy  = rem / 34;
            int xx  = rem - yy*34;
            int gh  = th0 + yy - 1;
            int gw  = tw0 + xx - 1;
            if (gh >= 0 && gh < 128 && gw >= 0 && gw < 128)
                v = x[((size_t)bt*16 + c)*HW + gh*128 + gw];
        }
        pf[j] = v;
    }

    ull acc[2][4];
#pragma unroll
    for (int c = 0; c < 2; ++c) {
        int q = cg*2 + c;
        ull b2 = pk2(s_b[2*q], s_b[2*q + 1]);
#pragma unroll
        for (int p = 0; p < 4; ++p) acc[c][p] = b2;
    }

#pragma unroll 1
    for (int half = 0; half < 2; ++half) {
        const int iclo = half*8;
        for (int ic = iclo; ic < iclo + 8; ++ic) {
            const float* base = s_in + ic*210 + py*35 + x0;
            ull pkk[3][6];
#pragma unroll
            for (int ky = 0; ky < 3; ++ky)
#pragma unroll
                for (int j = 0; j < 6; ++j) {
                    float v = base[ky*35 + j];
                    pkk[ky][j] = pk2(v, v);
                }
#pragma unroll
            for (int c = 0; c < 2; ++c) {
                const ull* wp = s_w2 + ((cg*2 + c)*16 + ic)*10;
                ulonglong2 wA = *(const ulonglong2*)wp;
                ulonglong2 wB = *(const ulonglong2*)(wp + 2);
                ulonglong2 wC = *(const ulonglong2*)(wp + 4);
                ulonglong2 wD = *(const ulonglong2*)(wp + 6);
                ull w8 = wp[8];
#pragma unroll
                for (int px = 0; px < 4; ++px) {
                    ull a = acc[c][px];
                    fma2(a, pkk[0][px+0], wA.x);
                    fma2(a, pkk[0][px+1], wA.y);
                    fma2(a, pkk[0][px+2], wB.x);
                    fma2(a, pkk[1][px+0], wB.y);
                    fma2(a, pkk[1][px+1], wC.x);
                    fma2(a, pkk[1][px+2], wC.y);
                    fma2(a, pkk[2][px+0], wD.x);
                    fma2(a, pkk[2][px+1], wD.y);
                    fma2(a, pkk[2][px+2], w8);
                    acc[c][px] = a;
                }
            }
        }
        if (half == 0) {
#pragma unroll
            for (int j = 0; j < 13; ++j) {
                int idx = tid + j*128;
                if (idx < 1632) {
                    int c   = 8 + idx / 204;
                    int rem = idx - (c - 8)*204;
                    int yy  = rem / 34;
                    int xx  = rem - yy*34;
                    s_in[c*210 + yy*35 + xx] = pf[j];
                }
            }
            __syncthreads();
        }
    }

    const int oh = th0 + py;
    const int ow = tw0 + x0;
    float* outp = TOV ? g_v : out_final;
#pragma unroll
    for (int c = 0; c < 2; ++c) {
        int chA = (cg*2 + c)*2;
        size_t offA = ((size_t)bt*16 + chA)*HW + oh*128 + ow;
        float2 v0 = upk(acc[c][0]);
        float2 v1 = upk(acc[c][1]);
        float2 v2 = upk(acc[c][2]);
        float2 v3 = upk(acc[c][3]);
        *(float4*)(outp + offA)      = make_float4(v0.x, v1.x, v2.x, v3.x);
        *(float4*)(outp + offA + HW) = make_float4(v0.y, v1.y, v2.y, v3.y);
    }
}

// ---------------- QK^T: 2-stage pipelined staging, FFMA2 inner -----------
__global__ void __launch_bounds__(256, 3) qk_kernel()
{
    extern __shared__ float smf[];      // stage stride 8704 floats
    const int bh = blockIdx.y;
    const int b  = bh >> 3, h = bh & 7;
    const int split = blockIdx.x;
    const int tid = threadIdx.x;
    const int ty = tid >> 4, tx = tid & 15;

    int st_t[4], st_kq[4];
#pragma unroll
    for (int j = 0; j < 4; ++j) {
        int i = tid + j*256;
        st_t[j]  = i >> 4;
        st_kq[j] = (i & 15) << 2;
    }

    uint2 qr[4], kr[4];
    {
        const int kc = split*512;
#pragma unroll
        for (int j = 0; j < 4; ++j) {
            size_t base = ((size_t)((b*64 + st_t[j])*16 + h*2))*HW + kc + st_kq[j];
            qr[j] = *(const uint2*)(g_qh + base);
            kr[j] = *(const uint2*)(g_kh + base);
        }
    }

    ull acc2[4][2];
#pragma unroll
    for (int i = 0; i < 4; ++i) { acc2[i][0] = 0ULL; acc2[i][1] = 0ULL; }

    for (int sub = 0; sub < 8; ++sub) {
        float* Qs = smf + (sub & 1)*8704;
        float* Ks = Qs + 4352;
        __syncthreads();
#pragma unroll
        for (int j = 0; j < 4; ++j) {
            float2 q01 = __bfloat1622float2(*(const __nv_bfloat162*)&qr[j].x);
            float2 q23 = __bfloat1622float2(*(const __nv_bfloat162*)&qr[j].y);
            float2 k01 = __bfloat1622float2(*(const __nv_bfloat162*)&kr[j].x);
            float2 k23 = __bfloat1622float2(*(const __nv_bfloat162*)&kr[j].y);
            int t = st_t[j], kq = st_kq[j];
            Qs[(kq+0)*68 + t] = q01.x; Qs[(kq+1)*68 + t] = q01.y;
            Qs[(kq+2)*68 + t] = q23.x; Qs[(kq+3)*68 + t] = q23.y;
            Ks[(kq+0)*68 + t] = k01.x; Ks[(kq+1)*68 + t] = k01.y;
            Ks[(kq+2)*68 + t] = k23.x; Ks[(kq+3)*68 + t] = k23.y;
        }
        if (sub < 7) {
            const int kc = split*512 + (sub+1)*64;
#pragma unroll
            for (int j = 0; j < 4; ++j) {
                size_t base = ((size_t)((b*64 + st_t[j])*16 + h*2))*HW + kc + st_kq[j];
                qr[j] = *(const uint2*)(g_qh + base);
                kr[j] = *(const uint2*)(g_kh + base);
            }
        }
        __syncthreads();
#pragma unroll 8
        for (int kk = 0; kk < 64; ++kk) {
            float4 a = *(const float4*)(Qs + kk*68 + ty*4);
            ulonglong2 bp = *(const ulonglong2*)(Ks + kk*68 + tx*4);
            ull a0 = pk2(a.x, a.x);
            ull a1 = pk2(a.y, a.y);
            ull a2 = pk2(a.z, a.z);
            ull a3 = pk2(a.w, a.w);
            fma2(acc2[0][0], a0, bp.x); fma2(acc2[0][1], a0, bp.y);
            fma2(acc2[1][0], a1, bp.x); fma2(acc2[1][1], a1, bp.y);
            fma2(acc2[2][0], a2, bp.x); fma2(acc2[2][1], a2, bp.y);
            fma2(acc2[3][0], a3, bp.x); fma2(acc2[3][1], a3, bp.y);
        }
    }

    float* dst = g_part + ((size_t)(split*16 + bh))*4096;
#pragma unroll
    for (int i = 0; i < 4; ++i) {
        float2 lo = upk(acc2[i][0]);
        float2 hi = upk(acc2[i][1]);
        *(float4*)(dst + (ty*4 + i)*64 + tx*4) = make_float4(lo.x, lo.y, hi.x, hi.y);
    }
}

// ---------------- split-reduce + causal softmax ----------------
__global__ void softmax_kernel()
{
    const int bh = blockIdx.y;
    const int t  = blockIdx.x;
    const int s  = threadIdx.x;

    float ssum = 0.f;
    for (int sp = 0; sp < 64; ++sp)
        ssum += g_part[((size_t)(sp*16 + bh)*64 + t)*64 + s];

    const float scale = rsqrtf(32768.0f);
    const bool valid = (s <= t);
    float logit = valid ? ssum * scale : -INFINITY;

    __shared__ float red[64];
    red[s] = logit;
    __syncthreads();
    for (int off = 32; off > 0; off >>= 1) {
        if (s < off) red[s] = fmaxf(red[s], red[s + off]);
        __syncthreads();
    }
    float mx = red[0];
    __syncthreads();
    float e = valid ? expf(logit - mx) : 0.f;
    red[s] = e;
    __syncthreads();
    for (int off = 32; off > 0; off >>= 1) {
        if (s < off) red[s] += red[s + off];
        __syncthreads();
    }
    float p = e / red[0];
    g_att[(bh*64 + s)*64 + t] = p;   // 0 for s > t
}

// ---------------- y = att @ V: 2 d/thread, MLP=4 v batching ---------------
__global__ void __launch_bounds__(256, 2) av_kernel()
{
    __shared__ __align__(16) float sa[64][32];
    const int bh = blockIdx.z;
    const int b  = bh >> 3, h = bh & 7;
    const int thalf = blockIdx.y;
    const int t0 = thalf * 32;
    const int smax = thalf ? 64 : 32;
    const int d0 = blockIdx.x*512 + threadIdx.x*2;

    for (int i = threadIdx.x; i < smax*8; i += 256) {
        int s = i >> 3; int tg = i & 7;
        *(float4*)&sa[s][tg*4] = *(const float4*)(g_att + (bh*64 + s)*64 + t0 + tg*4);
    }
    __syncthreads();

    ull acc[16][2];
#pragma unroll
    for (int g = 0; g < 16; ++g) { acc[g][0] = 0ULL; acc[g][1] = 0ULL; }

    const size_t vbase = ((size_t)(b*64*16 + h*2))*HW + d0;
    for (int s0 = 0; s0 < smax; s0 += 4) {
        float2 vv[4];
#pragma unroll
        for (int j = 0; j < 4; ++j)
            vv[j] = *(const float2*)(g_v + vbase + (size_t)(s0 + j)*16*HW);
#pragma unroll
        for (int j = 0; j < 4; ++j) {
            ull va = pk2(vv[j].x, vv[j].x);
            ull vb = pk2(vv[j].y, vv[j].y);
            const int s = s0 + j;
#pragma unroll
            for (int g = 0; g < 8; ++g) {
                ulonglong2 ap = *(const ulonglong2*)&sa[s][g*4];
                fma2(acc[g*2+0][0], ap.x, va);
                fma2(acc[g*2+0][1], ap.x, vb);
                fma2(acc[g*2+1][0], ap.y, va);
                fma2(acc[g*2+1][1], ap.y, vb);
            }
        }
    }

#pragma unroll
    for (int g = 0; g < 16; ++g) {
        float2 oA = upk(acc[g][0]);
        float2 oB = upk(acc[g][1]);
        int t = t0 + g*2;
        *(float2*)(g_q + ((size_t)((b*64 + t  )*16 + h*2))*HW + d0) = make_float2(oA.x, oB.x);
        *(float2*)(g_q + ((size_t)((b*64 + t+1)*16 + h*2))*HW + d0) = make_float2(oA.y, oB.y);
    }
}

// ---------------- launch ----------------
extern "C" void kernel_launch(void* const* d_in, const int* in_sizes, int n_in,
                              void* d_out, int out_size)
{
    const float* x  = (const float*)d_in[0];
    const float* wq = (const float*)d_in[1];
    const float* bq = (const float*)d_in[2];
    const float* wk = (const float*)d_in[3];
    const float* bk = (const float*)d_in[4];
    const float* wv = (const float*)d_in[5];
    const float* bv = (const float*)d_in[6];
    const float* wo = (const float*)d_in[7];
    const float* bo = (const float*)d_in[8];
    float* out = (float*)d_out;

    const int smemC  = 8*160*8 + 16*210*4 + 16*4;  // 23744 B
    const int smemQK = 2 * 2 * 4352 * 4;           // 69632 B
    cudaFuncSetAttribute(qkconv_mma_kernel, cudaFuncAttributeMaxDynamicSharedMemorySize, MSMEM);
    cudaFuncSetAttribute(conv3x3_kernel<true>,  cudaFuncAttributeMaxDynamicSharedMemorySize, smemC);
    cudaFuncSetAttribute(conv3x3_kernel<false>, cudaFuncAttributeMaxDynamicSharedMemorySize, smemC);
    cudaFuncSetAttribute(qk_kernel, cudaFuncAttributeMaxDynamicSharedMemorySize, smemQK);

    qkconv_mma_kernel<<<dim3(64, 128), 128, MSMEM>>>(x, wq, bq, wk, bk);
    conv3x3_kernel<true><<<dim3(128, 128), 128, smemC>>>(x, wv, bv, nullptr);
    qk_kernel<<<dim3(64, 16), 256, smemQK>>>();
    softmax_kernel<<<dim3(64, 16), 64>>>();
    av_kernel<<<dim3(64, 2, 16), 256>>>();
    conv3x3_kernel<false><<<dim3(128, 128), 128, smemC>>>(nullptr, wo, bo, out);
}